// round 16
// baseline (speedup 1.0000x reference)
#include <cuda_runtime.h>
#include <cuda_bf16.h>
#include <cstdint>

// ---------------------------------------------------------------------------
// PatchCore scoring via HMMA (mma.sync m16n8k16 bf16, fp32 accum):
//   score[n] = 1 - max_m cos(p_n, mem_m);  image = mean(top-k(score))
// R16 = R15 with the middle k-loop FULLY unrolled (was unroll 3) so ptxas can
//       software-pipeline LDSM issue across the whole chunk body.
// ---------------------------------------------------------------------------

#define NPATCH 4096
#define CDIM   176
#define MMEM   131072
#define KPAD   184
#define MTILE  256
#define NTILE  128
#define A_ELEMS (MTILE * KPAD)            // 47104
#define B_ELEMS (NTILE * KPAD)            // 23552
#define A_BYTES (A_ELEMS * 2)             // 94208
#define B_BYTES (B_ELEMS * 2)             // 47104
#define NPTILES (NPATCH / MTILE)          // 16
#define NCHUNKS (MMEM / NTILE)            // 1024
#define SPLITS  64
#define CHUNKS_PER_JOB (NCHUNKS / SPLITS) // 16
#define NJOBS   (NPTILES * SPLITS)        // 1024
#define PCTAS   148
#define KSTEPS  (CDIM / 16)               // 11
#define ROWB    (KPAD * 2)                // 368
#define ENC_NEG_INF 0x007FFFFFu

// SMEM layout (dynamic)
#define SM_MB_A   0
#define SM_MB_B0  8
#define SM_MB_B1  16
#define SM_MB_E0  24
#define SM_MB_E1  32
#define SM_MB_AE  40
#define SM_A      1024
#define SM_B0     (SM_A  + A_BYTES)
#define SM_B1     (SM_B0 + B_BYTES)
#define SM_TOTAL  (SM_B1 + B_BYTES)       // 189440

__device__ __nv_bfloat16 g_pa[NPTILES * A_ELEMS];
__device__ __nv_bfloat16 g_mb[(size_t)NCHUNKS * B_ELEMS];
__device__ unsigned g_max_enc[NPATCH];

// ---- helpers ---------------------------------------------------------------
__device__ __forceinline__ unsigned enc_f(float f) {
    unsigned u = __float_as_uint(f);
    return (u & 0x80000000u) ? ~u : (u | 0x80000000u);
}
__device__ __forceinline__ float dec_f(unsigned e) {
    unsigned u = (e & 0x80000000u) ? (e & 0x7FFFFFFFu) : ~e;
    return __uint_as_float(u);
}
__device__ __forceinline__ uint32_t smem_u32(const void* p) {
    uint32_t a;
    asm("{ .reg .u64 t; cvta.to.shared.u64 t, %1; cvt.u32.u64 %0, t; }" : "=r"(a) : "l"(p));
    return a;
}

#define MBAR_INIT(a, n) asm volatile("mbarrier.init.shared.b64 [%0], %1;" :: "r"(a), "r"(n) : "memory")
#define MBAR_ARRIVE(a)  asm volatile("mbarrier.arrive.shared.b64 _, [%0];" :: "r"(a) : "memory")
#define MBAR_EXPECT(a, b) asm volatile("mbarrier.arrive.expect_tx.shared.b64 _, [%0], %1;" :: "r"(a), "r"(b) : "memory")
#define MBAR_WAIT(a, ph) do { \
    uint32_t _m = (a), _p = (ph), _d; \
    asm volatile("{\n\t.reg .pred p;\n\tmbarrier.try_wait.parity.acquire.cta.shared::cta.b64 p, [%1], %2;\n\tselp.b32 %0,1,0,p;\n\t}" \
        : "=r"(_d) : "r"(_m), "r"(_p) : "memory"); \
    if (!_d) { \
        asm volatile("{\n\t.reg .pred P1;\n\tWL_%=:\n\tmbarrier.try_wait.parity.acquire.cta.shared::cta.b64 P1, [%0], %1, 0x989680;\n\t@P1 bra.uni WD_%=;\n\tbra.uni WL_%=;\n\tWD_%=:\n\t}" \
            :: "r"(_m), "r"(_p) : "memory"); \
    } } while (0)

__device__ __forceinline__ void bulk_g2s(uint32_t dst, const void* src, uint32_t bytes, uint32_t mbar) {
    asm volatile("cp.async.bulk.shared::cta.global.mbarrier::complete_tx::bytes [%0], [%1], %2, [%3];"
                 :: "r"(dst), "l"(src), "r"(bytes), "r"(mbar) : "memory");
}
__device__ __forceinline__ void ldsm4(uint32_t& r0, uint32_t& r1, uint32_t& r2, uint32_t& r3, uint32_t addr) {
    asm volatile("ldmatrix.sync.aligned.m8n8.x4.shared.b16 {%0,%1,%2,%3}, [%4];"
                 : "=r"(r0), "=r"(r1), "=r"(r2), "=r"(r3) : "r"(addr));
}
__device__ __forceinline__ void mma16816(float* c, const uint32_t* a, const uint32_t* b) {
    asm volatile("mma.sync.aligned.m16n8k16.row.col.f32.bf16.bf16.f32 "
                 "{%0,%1,%2,%3}, {%4,%5,%6,%7}, {%8,%9}, {%0,%1,%2,%3};"
                 : "+f"(c[0]), "+f"(c[1]), "+f"(c[2]), "+f"(c[3])
                 : "r"(a[0]), "r"(a[1]), "r"(a[2]), "r"(a[3]), "r"(b[0]), "r"(b[1]));
}
__device__ __forceinline__ void mma16816_c0(float* c, const uint32_t* a, const uint32_t* b, float z) {
    asm volatile("mma.sync.aligned.m16n8k16.row.col.f32.bf16.bf16.f32 "
                 "{%0,%1,%2,%3}, {%4,%5,%6,%7}, {%8,%9}, {%10,%10,%10,%10};"
                 : "=f"(c[0]), "=f"(c[1]), "=f"(c[2]), "=f"(c[3])
                 : "r"(a[0]), "r"(a[1]), "r"(a[2]), "r"(a[3]), "r"(b[0]), "r"(b[1]), "f"(z));
}

// ---- prep: normalize rows -> bf16 padded row-major tiles (vectorized) -------
__device__ __forceinline__ void prep_one_row(const float* __restrict__ row,
                                             __nv_bfloat16* __restrict__ out_row, int lane) {
    const float4* r4 = (const float4*)row;
    float4 v0 = r4[lane];
    float4 v1 = make_float4(0.f, 0.f, 0.f, 0.f);
    if (lane < 12) v1 = r4[lane + 32];
    float ss = v0.x * v0.x + v0.y * v0.y + v0.z * v0.z + v0.w * v0.w
             + v1.x * v1.x + v1.y * v1.y + v1.z * v1.z + v1.w * v1.w;
#pragma unroll
    for (int o = 16; o; o >>= 1) ss += __shfl_xor_sync(0xFFFFFFFFu, ss, o);
    float inv = 1.f / (sqrtf(ss) + 1e-6f);

    uint2* out2 = (uint2*)out_row;
    {
        __nv_bfloat162 a0 = __floats2bfloat162_rn(v0.x * inv, v0.y * inv);
        __nv_bfloat162 a1 = __floats2bfloat162_rn(v0.z * inv, v0.w * inv);
        uint2 p;
        p.x = *(const unsigned*)&a0;
        p.y = *(const unsigned*)&a1;
        out2[lane] = p;
    }
    if (lane < 12) {
        __nv_bfloat162 a0 = __floats2bfloat162_rn(v1.x * inv, v1.y * inv);
        __nv_bfloat162 a1 = __floats2bfloat162_rn(v1.z * inv, v1.w * inv);
        uint2 p;
        p.x = *(const unsigned*)&a0;
        p.y = *(const unsigned*)&a1;
        out2[lane + 32] = p;
    }
    if (lane == 12) {
        *(uint4*)(out_row + CDIM) = make_uint4(0u, 0u, 0u, 0u);  // pad cols 176..183
    }
}

__global__ void prep_all_kernel(const float* __restrict__ patch,
                                const float* __restrict__ mem) {
    int warp = (blockIdx.x * blockDim.x + threadIdx.x) >> 5;
    int lane = threadIdx.x & 31;
    if (warp < NPATCH) {
        int tile = warp / MTILE, r = warp % MTILE;
        prep_one_row(patch + (size_t)warp * CDIM,
                     g_pa + (size_t)tile * A_ELEMS + (size_t)r * KPAD, lane);
        if (lane == 0) g_max_enc[warp] = ENC_NEG_INF;
    } else if (warp < NPATCH + MMEM) {
        int m = warp - NPATCH;
        int tile = m / NTILE, r = m % NTILE;
        prep_one_row(mem + (size_t)m * CDIM,
                     g_mb + (size_t)tile * B_ELEMS + (size_t)r * KPAD, lane);
    }
}

// ---- main: persistent HMMA GEMM (256x128 CTA tile) with fused row-max --------
__global__ void __launch_bounds__(256, 1) hmma_gemm_max_kernel() {
    extern __shared__ char smem[];
    __shared__ unsigned red[MTILE];
    const uint32_t sb = smem_u32(smem);
    const int tid  = threadIdx.x;
    const int lane = tid & 31;
    const int wid  = tid >> 5;
    const int m0   = (wid >> 1) * 64;
    const int n0   = (wid & 1) * 64;
    const int bid  = blockIdx.x;

    if (tid == 0) {
        MBAR_INIT(sb + SM_MB_A, 1);
        MBAR_INIT(sb + SM_MB_B0, 1);
        MBAR_INIT(sb + SM_MB_B1, 1);
        MBAR_INIT(sb + SM_MB_E0, 8);
        MBAR_INIT(sb + SM_MB_E1, 8);
        MBAR_INIT(sb + SM_MB_AE, 8);
    }
    __syncthreads();

    if (tid == 0) {
        MBAR_EXPECT(sb + SM_MB_A, A_BYTES);
        bulk_g2s(sb + SM_A, g_pa + (size_t)(bid >> 6) * A_ELEMS, A_BYTES, sb + SM_MB_A);
        MBAR_EXPECT(sb + SM_MB_B0, B_BYTES);
        bulk_g2s(sb + SM_B0, g_mb + (size_t)((bid & 63) * CHUNKS_PER_JOB) * B_ELEMS,
                 B_BYTES, sb + SM_MB_B0);
        MBAR_EXPECT(sb + SM_MB_B1, B_BYTES);
        bulk_g2s(sb + SM_B1, g_mb + (size_t)((bid & 63) * CHUNKS_PER_JOB + 1) * B_ELEMS,
                 B_BYTES, sb + SM_MB_B1);
    }

    const uint32_t a_base = sb + SM_A +
        (uint32_t)(m0 + (lane & 15)) * ROWB + ((lane >> 4) << 4);
    const uint32_t b_lane_off =
        (uint32_t)(n0 + ((lane >> 4) << 3) + (lane & 7)) * ROWB + (((lane >> 3) & 1) << 4);

    int t = 0;  // continuous B-chunk sequence counter
#pragma unroll 1
    for (int w = 0, job = bid; job < NJOBS; w++, job += PCTAS) {
        const int ptile = job >> 6;

        float rm[4][2];
#pragma unroll
        for (int f = 0; f < 4; f++) { rm[f][0] = -3.0e38f; rm[f][1] = -3.0e38f; }

        MBAR_WAIT(sb + SM_MB_A, (uint32_t)(w & 1));

#pragma unroll 1
        for (int c = 0; c < CHUNKS_PER_JOB; c++, t++) {
            const int buf = t & 1;
            const uint32_t ph = (uint32_t)((t >> 1) & 1);
            const uint32_t mb_b = sb + (buf ? SM_MB_B1 : SM_MB_B0);
            const uint32_t mb_e = sb + (buf ? SM_MB_E1 : SM_MB_E0);
            const uint32_t b_base = sb + (buf ? SM_B1 : SM_B0) + b_lane_off;

            MBAR_WAIT(mb_b, ph);

            float acc[4][8][4];
            uint32_t a[4][4], b[8][2];

#define LOAD_FRAGS(ks) do {                                                     \
    _Pragma("unroll")                                                           \
    for (int f = 0; f < 4; f++)                                                 \
        ldsm4(a[f][0], a[f][1], a[f][2], a[f][3],                               \
              a_base + (uint32_t)(f * 16) * ROWB + (ks) * 32);                  \
    _Pragma("unroll")                                                           \
    for (int g2 = 0; g2 < 4; g2++) {                                            \
        uint32_t r0, r1, r2, r3;                                                \
        ldsm4(r0, r1, r2, r3,                                                   \
              b_base + (uint32_t)(g2 * 16) * ROWB + (ks) * 32);                 \
        b[2 * g2][0] = r0; b[2 * g2][1] = r1;                                   \
        b[2 * g2 + 1][0] = r2; b[2 * g2 + 1][1] = r3;                           \
    } } while (0)

            // ks = 0: init accumulators directly from MMA (C = 0)
            LOAD_FRAGS(0);
#pragma unroll
            for (int f = 0; f < 4; f++)
#pragma unroll
                for (int g = 0; g < 8; g++)
                    mma16816_c0(acc[f][g], a[f], b[g], 0.0f);

            // ks = 1..9: FULL unroll -> ptxas pipelines LDSM across the body
#pragma unroll
            for (int ks = 1; ks < KSTEPS - 1; ks++) {
                LOAD_FRAGS(ks);
#pragma unroll
                for (int f = 0; f < 4; f++)
#pragma unroll
                    for (int g = 0; g < 8; g++)
                        mma16816(acc[f][g], a[f], b[g]);
            }

            // ks = 10: last fragment loads, release buffers BEFORE tail MMAs
            LOAD_FRAGS(KSTEPS - 1);
            if (lane == 0) {
                MBAR_ARRIVE(mb_e);
                if (c == CHUNKS_PER_JOB - 1) MBAR_ARRIVE(sb + SM_MB_AE);
            }
#pragma unroll
            for (int f = 0; f < 4; f++)
#pragma unroll
                for (int g = 0; g < 8; g++)
                    mma16816(acc[f][g], a[f], b[g]);
#undef LOAD_FRAGS

            // producer refill (earlier TMA issue), then per-lane fold
            if (tid == 0) {
                const int s = t + 2;
                const int job2 = bid + (s >> 4) * PCTAS;
                if (job2 < NJOBS) {
                    const int gch = (job2 & 63) * CHUNKS_PER_JOB + (s & 15);
                    MBAR_WAIT(mb_e, ph);
                    MBAR_EXPECT(mb_b, B_BYTES);
                    bulk_g2s(sb + (buf ? SM_B1 : SM_B0),
                             g_mb + (size_t)gch * B_ELEMS, B_BYTES, mb_b);
                }
            }

#pragma unroll
            for (int f = 0; f < 4; f++)
#pragma unroll
                for (int g = 0; g < 8; g++) {
                    rm[f][0] = fmaxf(rm[f][0], fmaxf(acc[f][g][0], acc[f][g][1]));
                    rm[f][1] = fmaxf(rm[f][1], fmaxf(acc[f][g][2], acc[f][g][3]));
                }
        }

        // overlap next-job A load with epilogue
        if (tid == 0 && job + PCTAS < NJOBS) {
            MBAR_WAIT(sb + SM_MB_AE, (uint32_t)(w & 1));
            MBAR_EXPECT(sb + SM_MB_A, A_BYTES);
            bulk_g2s(sb + SM_A, g_pa + (size_t)((job + PCTAS) >> 6) * A_ELEMS,
                     A_BYTES, sb + SM_MB_A);
        }

        // job epilogue: quad reduce, CTA reduce, global atomics
#pragma unroll
        for (int f = 0; f < 4; f++) {
#pragma unroll
            for (int h = 0; h < 2; h++) {
                rm[f][h] = fmaxf(rm[f][h], __shfl_xor_sync(0xFFFFFFFFu, rm[f][h], 1));
                rm[f][h] = fmaxf(rm[f][h], __shfl_xor_sync(0xFFFFFFFFu, rm[f][h], 2));
            }
        }
        if (tid < 128) { red[tid] = ENC_NEG_INF; red[tid + 128] = ENC_NEG_INF; }
        __syncthreads();
        if ((lane & 3) == 0) {
#pragma unroll
            for (int f = 0; f < 4; f++) {
                int r = m0 + f * 16 + (lane >> 2);
                atomicMax(&red[r],     enc_f(rm[f][0]));
                atomicMax(&red[r + 8], enc_f(rm[f][1]));
            }
        }
        __syncthreads();
        if (tid < 128) {
            atomicMax(&g_max_enc[ptile * MTILE + tid], red[tid]);
            atomicMax(&g_max_enc[ptile * MTILE + tid + 128], red[tid + 128]);
        }
        __syncthreads();
    }
}

// ---- finalize: register-resident top-k --------------------------------------
__global__ void finalize_kernel(const int* __restrict__ topk_ptr,
                                float* __restrict__ out, int out_size) {
    __shared__ unsigned long long wb[8];
    __shared__ unsigned long long winner;
    const int tid  = threadIdx.x;
    const int lane = tid & 31;
    const int wid  = tid >> 5;

    float r[16];
#pragma unroll
    for (int i = 0; i < 16; i++) {
        int idx = i * 256 + tid;
        float s = 1.0f - dec_f(g_max_enc[idx]);
        r[i] = s;
        if (out_size >= NPATCH) out[idx] = s;
    }

    int k = topk_ptr ? *topk_ptr : 10;
    if (k < 1) k = 1;
    if (k > NPATCH) k = NPATCH;

    float sum = 0.f;
#pragma unroll 1
    for (int p = 0; p < k; p++) {
        float best = r[0];
        int bi = 0;
#pragma unroll
        for (int i = 1; i < 16; i++)
            if (r[i] > best) { best = r[i]; bi = i; }
        unsigned long long pk =
            ((unsigned long long)enc_f(best) << 32) | (unsigned)((bi << 8) | tid);
#pragma unroll
        for (int o = 16; o; o >>= 1) {
            unsigned long long q = __shfl_xor_sync(0xFFFFFFFFu, pk, o);
            if (q > pk) pk = q;
        }
        if (lane == 0) wb[wid] = pk;
        __syncthreads();
        if (tid == 0) {
            unsigned long long m = wb[0];
#pragma unroll
            for (int w2 = 1; w2 < 8; w2++) if (wb[w2] > m) m = wb[w2];
            winner = m;
            sum += dec_f((unsigned)(m >> 32));
        }
        __syncthreads();
        unsigned widx = (unsigned)(winner & 0xFFFFFFFFu);
        if ((widx & 255u) == (unsigned)tid) {
            int i0 = (int)(widx >> 8);
#pragma unroll
            for (int i = 0; i < 16; i++)
                if (i == i0) r[i] = -3.0e38f;
        }
        __syncthreads();
    }

    if (tid == 0) {
        float img = sum / (float)k;
        if (out_size >= NPATCH + 1) out[NPATCH] = img;
        else if (out_size < NPATCH && out_size >= 1) out[0] = img;
    }
}

// ---------------------------------------------------------------------------
extern "C" void kernel_launch(void* const* d_in, const int* in_sizes, int n_in,
                              void* d_out, int out_size) {
    const float* patch = (const float*)d_in[0];
    const float* mem   = (const float*)d_in[1];
    const int*   topk  = (n_in >= 3) ? (const int*)d_in[2] : nullptr;
    float* out = (float*)d_out;
    (void)in_sizes;

    const int total_warps = NPATCH + MMEM;
    prep_all_kernel<<<(total_warps * 32 + 255) / 256, 256>>>(patch, mem);

    cudaFuncSetAttribute(hmma_gemm_max_kernel,
                         cudaFuncAttributeMaxDynamicSharedMemorySize, SM_TOTAL);
    hmma_gemm_max_kernel<<<PCTAS, 256, SM_TOTAL>>>();

    finalize_kernel<<<1, 256>>>(topk, out, out_size);
}

// round 17
// speedup vs baseline: 1.0115x; 1.0115x over previous
#include <cuda_runtime.h>
#include <cuda_bf16.h>
#include <cstdint>

// ---------------------------------------------------------------------------
// PatchCore scoring via HMMA (mma.sync m16n8k16 bf16, fp32 accum):
//   score[n] = 1 - max_m cos(p_n, mem_m);  image = mean(top-k(score))
// FINAL (= R15/R13 gold, best measured 389.6us):
//   - prep: full-occupancy vectorized normalize->bf16 (DRAM-floor, ~23us)
//   - gemm: persistent 148 CTAs, 256x128 tile, 8 warps (64x64 each),
//           TMA double-buffered B ring continuous across jobs, cross-job A
//           overlap, mma-C0 accumulator init, early empty-arrive,
//           unroll-3 k-loop (measured optimum: 1->391.6, 3->389.6, 9->393.7)
//   - finalize: register-resident top-k
// ---------------------------------------------------------------------------

#define NPATCH 4096
#define CDIM   176
#define MMEM   131072
#define KPAD   184
#define MTILE  256
#define NTILE  128
#define A_ELEMS (MTILE * KPAD)            // 47104
#define B_ELEMS (NTILE * KPAD)            // 23552
#define A_BYTES (A_ELEMS * 2)             // 94208
#define B_BYTES (B_ELEMS * 2)             // 47104
#define NPTILES (NPATCH / MTILE)          // 16
#define NCHUNKS (MMEM / NTILE)            // 1024
#define SPLITS  64
#define CHUNKS_PER_JOB (NCHUNKS / SPLITS) // 16
#define NJOBS   (NPTILES * SPLITS)        // 1024
#define PCTAS   148
#define KSTEPS  (CDIM / 16)               // 11
#define ROWB    (KPAD * 2)                // 368
#define ENC_NEG_INF 0x007FFFFFu

// SMEM layout (dynamic)
#define SM_MB_A   0
#define SM_MB_B0  8
#define SM_MB_B1  16
#define SM_MB_E0  24
#define SM_MB_E1  32
#define SM_MB_AE  40
#define SM_A      1024
#define SM_B0     (SM_A  + A_BYTES)
#define SM_B1     (SM_B0 + B_BYTES)
#define SM_TOTAL  (SM_B1 + B_BYTES)       // 189440

__device__ __nv_bfloat16 g_pa[NPTILES * A_ELEMS];
__device__ __nv_bfloat16 g_mb[(size_t)NCHUNKS * B_ELEMS];
__device__ unsigned g_max_enc[NPATCH];

// ---- helpers ---------------------------------------------------------------
__device__ __forceinline__ unsigned enc_f(float f) {
    unsigned u = __float_as_uint(f);
    return (u & 0x80000000u) ? ~u : (u | 0x80000000u);
}
__device__ __forceinline__ float dec_f(unsigned e) {
    unsigned u = (e & 0x80000000u) ? (e & 0x7FFFFFFFu) : ~e;
    return __uint_as_float(u);
}
__device__ __forceinline__ uint32_t smem_u32(const void* p) {
    uint32_t a;
    asm("{ .reg .u64 t; cvta.to.shared.u64 t, %1; cvt.u32.u64 %0, t; }" : "=r"(a) : "l"(p));
    return a;
}

#define MBAR_INIT(a, n) asm volatile("mbarrier.init.shared.b64 [%0], %1;" :: "r"(a), "r"(n) : "memory")
#define MBAR_ARRIVE(a)  asm volatile("mbarrier.arrive.shared.b64 _, [%0];" :: "r"(a) : "memory")
#define MBAR_EXPECT(a, b) asm volatile("mbarrier.arrive.expect_tx.shared.b64 _, [%0], %1;" :: "r"(a), "r"(b) : "memory")
#define MBAR_WAIT(a, ph) do { \
    uint32_t _m = (a), _p = (ph), _d; \
    asm volatile("{\n\t.reg .pred p;\n\tmbarrier.try_wait.parity.acquire.cta.shared::cta.b64 p, [%1], %2;\n\tselp.b32 %0,1,0,p;\n\t}" \
        : "=r"(_d) : "r"(_m), "r"(_p) : "memory"); \
    if (!_d) { \
        asm volatile("{\n\t.reg .pred P1;\n\tWL_%=:\n\tmbarrier.try_wait.parity.acquire.cta.shared::cta.b64 P1, [%0], %1, 0x989680;\n\t@P1 bra.uni WD_%=;\n\tbra.uni WL_%=;\n\tWD_%=:\n\t}" \
            :: "r"(_m), "r"(_p) : "memory"); \
    } } while (0)

__device__ __forceinline__ void bulk_g2s(uint32_t dst, const void* src, uint32_t bytes, uint32_t mbar) {
    asm volatile("cp.async.bulk.shared::cta.global.mbarrier::complete_tx::bytes [%0], [%1], %2, [%3];"
                 :: "r"(dst), "l"(src), "r"(bytes), "r"(mbar) : "memory");
}
__device__ __forceinline__ void ldsm4(uint32_t& r0, uint32_t& r1, uint32_t& r2, uint32_t& r3, uint32_t addr) {
    asm volatile("ldmatrix.sync.aligned.m8n8.x4.shared.b16 {%0,%1,%2,%3}, [%4];"
                 : "=r"(r0), "=r"(r1), "=r"(r2), "=r"(r3) : "r"(addr));
}
__device__ __forceinline__ void mma16816(float* c, const uint32_t* a, const uint32_t* b) {
    asm volatile("mma.sync.aligned.m16n8k16.row.col.f32.bf16.bf16.f32 "
                 "{%0,%1,%2,%3}, {%4,%5,%6,%7}, {%8,%9}, {%0,%1,%2,%3};"
                 : "+f"(c[0]), "+f"(c[1]), "+f"(c[2]), "+f"(c[3])
                 : "r"(a[0]), "r"(a[1]), "r"(a[2]), "r"(a[3]), "r"(b[0]), "r"(b[1]));
}
__device__ __forceinline__ void mma16816_c0(float* c, const uint32_t* a, const uint32_t* b, float z) {
    asm volatile("mma.sync.aligned.m16n8k16.row.col.f32.bf16.bf16.f32 "
                 "{%0,%1,%2,%3}, {%4,%5,%6,%7}, {%8,%9}, {%10,%10,%10,%10};"
                 : "=f"(c[0]), "=f"(c[1]), "=f"(c[2]), "=f"(c[3])
                 : "r"(a[0]), "r"(a[1]), "r"(a[2]), "r"(a[3]), "r"(b[0]), "r"(b[1]), "f"(z));
}

// ---- prep: normalize rows -> bf16 padded row-major tiles (vectorized) -------
__device__ __forceinline__ void prep_one_row(const float* __restrict__ row,
                                             __nv_bfloat16* __restrict__ out_row, int lane) {
    const float4* r4 = (const float4*)row;
    float4 v0 = r4[lane];
    float4 v1 = make_float4(0.f, 0.f, 0.f, 0.f);
    if (lane < 12) v1 = r4[lane + 32];
    float ss = v0.x * v0.x + v0.y * v0.y + v0.z * v0.z + v0.w * v0.w
             + v1.x * v1.x + v1.y * v1.y + v1.z * v1.z + v1.w * v1.w;
#pragma unroll
    for (int o = 16; o; o >>= 1) ss += __shfl_xor_sync(0xFFFFFFFFu, ss, o);
    float inv = 1.f / (sqrtf(ss) + 1e-6f);

    uint2* out2 = (uint2*)out_row;
    {
        __nv_bfloat162 a0 = __floats2bfloat162_rn(v0.x * inv, v0.y * inv);
        __nv_bfloat162 a1 = __floats2bfloat162_rn(v0.z * inv, v0.w * inv);
        uint2 p;
        p.x = *(const unsigned*)&a0;
        p.y = *(const unsigned*)&a1;
        out2[lane] = p;
    }
    if (lane < 12) {
        __nv_bfloat162 a0 = __floats2bfloat162_rn(v1.x * inv, v1.y * inv);
        __nv_bfloat162 a1 = __floats2bfloat162_rn(v1.z * inv, v1.w * inv);
        uint2 p;
        p.x = *(const unsigned*)&a0;
        p.y = *(const unsigned*)&a1;
        out2[lane + 32] = p;
    }
    if (lane == 12) {
        *(uint4*)(out_row + CDIM) = make_uint4(0u, 0u, 0u, 0u);  // pad cols 176..183
    }
}

__global__ void prep_all_kernel(const float* __restrict__ patch,
                                const float* __restrict__ mem) {
    int warp = (blockIdx.x * blockDim.x + threadIdx.x) >> 5;
    int lane = threadIdx.x & 31;
    if (warp < NPATCH) {
        int tile = warp / MTILE, r = warp % MTILE;
        prep_one_row(patch + (size_t)warp * CDIM,
                     g_pa + (size_t)tile * A_ELEMS + (size_t)r * KPAD, lane);
        if (lane == 0) g_max_enc[warp] = ENC_NEG_INF;
    } else if (warp < NPATCH + MMEM) {
        int m = warp - NPATCH;
        int tile = m / NTILE, r = m % NTILE;
        prep_one_row(mem + (size_t)m * CDIM,
                     g_mb + (size_t)tile * B_ELEMS + (size_t)r * KPAD, lane);
    }
}

// ---- main: persistent HMMA GEMM (256x128 CTA tile) with fused row-max --------
__global__ void __launch_bounds__(256, 1) hmma_gemm_max_kernel() {
    extern __shared__ char smem[];
    __shared__ unsigned red[MTILE];
    const uint32_t sb = smem_u32(smem);
    const int tid  = threadIdx.x;
    const int lane = tid & 31;
    const int wid  = tid >> 5;
    const int m0   = (wid >> 1) * 64;
    const int n0   = (wid & 1) * 64;
    const int bid  = blockIdx.x;

    if (tid == 0) {
        MBAR_INIT(sb + SM_MB_A, 1);
        MBAR_INIT(sb + SM_MB_B0, 1);
        MBAR_INIT(sb + SM_MB_B1, 1);
        MBAR_INIT(sb + SM_MB_E0, 8);
        MBAR_INIT(sb + SM_MB_E1, 8);
        MBAR_INIT(sb + SM_MB_AE, 8);
    }
    __syncthreads();

    if (tid == 0) {
        MBAR_EXPECT(sb + SM_MB_A, A_BYTES);
        bulk_g2s(sb + SM_A, g_pa + (size_t)(bid >> 6) * A_ELEMS, A_BYTES, sb + SM_MB_A);
        MBAR_EXPECT(sb + SM_MB_B0, B_BYTES);
        bulk_g2s(sb + SM_B0, g_mb + (size_t)((bid & 63) * CHUNKS_PER_JOB) * B_ELEMS,
                 B_BYTES, sb + SM_MB_B0);
        MBAR_EXPECT(sb + SM_MB_B1, B_BYTES);
        bulk_g2s(sb + SM_B1, g_mb + (size_t)((bid & 63) * CHUNKS_PER_JOB + 1) * B_ELEMS,
                 B_BYTES, sb + SM_MB_B1);
    }

    const uint32_t a_base = sb + SM_A +
        (uint32_t)(m0 + (lane & 15)) * ROWB + ((lane >> 4) << 4);
    const uint32_t b_lane_off =
        (uint32_t)(n0 + ((lane >> 4) << 3) + (lane & 7)) * ROWB + (((lane >> 3) & 1) << 4);

    int t = 0;  // continuous B-chunk sequence counter
#pragma unroll 1
    for (int w = 0, job = bid; job < NJOBS; w++, job += PCTAS) {
        const int ptile = job >> 6;

        float rm[4][2];
#pragma unroll
        for (int f = 0; f < 4; f++) { rm[f][0] = -3.0e38f; rm[f][1] = -3.0e38f; }

        MBAR_WAIT(sb + SM_MB_A, (uint32_t)(w & 1));

#pragma unroll 1
        for (int c = 0; c < CHUNKS_PER_JOB; c++, t++) {
            const int buf = t & 1;
            const uint32_t ph = (uint32_t)((t >> 1) & 1);
            const uint32_t mb_b = sb + (buf ? SM_MB_B1 : SM_MB_B0);
            const uint32_t mb_e = sb + (buf ? SM_MB_E1 : SM_MB_E0);
            const uint32_t b_base = sb + (buf ? SM_B1 : SM_B0) + b_lane_off;

            MBAR_WAIT(mb_b, ph);

            float acc[4][8][4];
            uint32_t a[4][4], b[8][2];

#define LOAD_FRAGS(ks) do {                                                     \
    _Pragma("unroll")                                                           \
    for (int f = 0; f < 4; f++)                                                 \
        ldsm4(a[f][0], a[f][1], a[f][2], a[f][3],                               \
              a_base + (uint32_t)(f * 16) * ROWB + (ks) * 32);                  \
    _Pragma("unroll")                                                           \
    for (int g2 = 0; g2 < 4; g2++) {                                            \
        uint32_t r0, r1, r2, r3;                                                \
        ldsm4(r0, r1, r2, r3,                                                   \
              b_base + (uint32_t)(g2 * 16) * ROWB + (ks) * 32);                 \
        b[2 * g2][0] = r0; b[2 * g2][1] = r1;                                   \
        b[2 * g2 + 1][0] = r2; b[2 * g2 + 1][1] = r3;                           \
    } } while (0)

            // ks = 0: init accumulators directly from MMA (C = 0)
            LOAD_FRAGS(0);
#pragma unroll
            for (int f = 0; f < 4; f++)
#pragma unroll
                for (int g = 0; g < 8; g++)
                    mma16816_c0(acc[f][g], a[f], b[g], 0.0f);

            // ks = 1..9: unroll 3 (measured optimum) -> ptxas pipelines LDSM
#pragma unroll 3
            for (int ks = 1; ks < KSTEPS - 1; ks++) {
                LOAD_FRAGS(ks);
#pragma unroll
                for (int f = 0; f < 4; f++)
#pragma unroll
                    for (int g = 0; g < 8; g++)
                        mma16816(acc[f][g], a[f], b[g]);
            }

            // ks = 10: last fragment loads, release buffers BEFORE tail MMAs
            LOAD_FRAGS(KSTEPS - 1);
            if (lane == 0) {
                MBAR_ARRIVE(mb_e);
                if (c == CHUNKS_PER_JOB - 1) MBAR_ARRIVE(sb + SM_MB_AE);
            }
#pragma unroll
            for (int f = 0; f < 4; f++)
#pragma unroll
                for (int g = 0; g < 8; g++)
                    mma16816(acc[f][g], a[f], b[g]);
#undef LOAD_FRAGS

            // producer refill (earlier TMA issue), then per-lane fold
            if (tid == 0) {
                const int s = t + 2;
                const int job2 = bid + (s >> 4) * PCTAS;
                if (job2 < NJOBS) {
                    const int gch = (job2 & 63) * CHUNKS_PER_JOB + (s & 15);
                    MBAR_WAIT(mb_e, ph);
                    MBAR_EXPECT(mb_b, B_BYTES);
                    bulk_g2s(sb + (buf ? SM_B1 : SM_B0),
                             g_mb + (size_t)gch * B_ELEMS, B_BYTES, mb_b);
                }
            }

#pragma unroll
            for (int f = 0; f < 4; f++)
#pragma unroll
                for (int g = 0; g < 8; g++) {
                    rm[f][0] = fmaxf(rm[f][0], fmaxf(acc[f][g][0], acc[f][g][1]));
                    rm[f][1] = fmaxf(rm[f][1], fmaxf(acc[f][g][2], acc[f][g][3]));
                }
        }

        // overlap next-job A load with epilogue
        if (tid == 0 && job + PCTAS < NJOBS) {
            MBAR_WAIT(sb + SM_MB_AE, (uint32_t)(w & 1));
            MBAR_EXPECT(sb + SM_MB_A, A_BYTES);
            bulk_g2s(sb + SM_A, g_pa + (size_t)((job + PCTAS) >> 6) * A_ELEMS,
                     A_BYTES, sb + SM_MB_A);
        }

        // job epilogue: quad reduce, CTA reduce, global atomics
#pragma unroll
        for (int f = 0; f < 4; f++) {
#pragma unroll
            for (int h = 0; h < 2; h++) {
                rm[f][h] = fmaxf(rm[f][h], __shfl_xor_sync(0xFFFFFFFFu, rm[f][h], 1));
                rm[f][h] = fmaxf(rm[f][h], __shfl_xor_sync(0xFFFFFFFFu, rm[f][h], 2));
            }
        }
        if (tid < 128) { red[tid] = ENC_NEG_INF; red[tid + 128] = ENC_NEG_INF; }
        __syncthreads();
        if ((lane & 3) == 0) {
#pragma unroll
            for (int f = 0; f < 4; f++) {
                int r = m0 + f * 16 + (lane >> 2);
                atomicMax(&red[r],     enc_f(rm[f][0]));
                atomicMax(&red[r + 8], enc_f(rm[f][1]));
            }
        }
        __syncthreads();
        if (tid < 128) {
            atomicMax(&g_max_enc[ptile * MTILE + tid], red[tid]);
            atomicMax(&g_max_enc[ptile * MTILE + tid + 128], red[tid + 128]);
        }
        __syncthreads();
    }
}

// ---- finalize: register-resident top-k --------------------------------------
__global__ void finalize_kernel(const int* __restrict__ topk_ptr,
                                float* __restrict__ out, int out_size) {
    __shared__ unsigned long long wb[8];
    __shared__ unsigned long long winner;
    const int tid  = threadIdx.x;
    const int lane = tid & 31;
    const int wid  = tid >> 5;

    float r[16];
#pragma unroll
    for (int i = 0; i < 16; i++) {
        int idx = i * 256 + tid;
        float s = 1.0f - dec_f(g_max_enc[idx]);
        r[i] = s;
        if (out_size >= NPATCH) out[idx] = s;
    }

    int k = topk_ptr ? *topk_ptr : 10;
    if (k < 1) k = 1;
    if (k > NPATCH) k = NPATCH;

    float sum = 0.f;
#pragma unroll 1
    for (int p = 0; p < k; p++) {
        float best = r[0];
        int bi = 0;
#pragma unroll
        for (int i = 1; i < 16; i++)
            if (r[i] > best) { best = r[i]; bi = i; }
        unsigned long long pk =
            ((unsigned long long)enc_f(best) << 32) | (unsigned)((bi << 8) | tid);
#pragma unroll
        for (int o = 16; o; o >>= 1) {
            unsigned long long q = __shfl_xor_sync(0xFFFFFFFFu, pk, o);
            if (q > pk) pk = q;
        }
        if (lane == 0) wb[wid] = pk;
        __syncthreads();
        if (tid == 0) {
            unsigned long long m = wb[0];
#pragma unroll
            for (int w2 = 1; w2 < 8; w2++) if (wb[w2] > m) m = wb[w2];
            winner = m;
            sum += dec_f((unsigned)(m >> 32));
        }
        __syncthreads();
        unsigned widx = (unsigned)(winner & 0xFFFFFFFFu);
        if ((widx & 255u) == (unsigned)tid) {
            int i0 = (int)(widx >> 8);
#pragma unroll
            for (int i = 0; i < 16; i++)
                if (i == i0) r[i] = -3.0e38f;
        }
        __syncthreads();
    }

    if (tid == 0) {
        float img = sum / (float)k;
        if (out_size >= NPATCH + 1) out[NPATCH] = img;
        else if (out_size < NPATCH && out_size >= 1) out[0] = img;
    }
}

// ---------------------------------------------------------------------------
extern "C" void kernel_launch(void* const* d_in, const int* in_sizes, int n_in,
                              void* d_out, int out_size) {
    const float* patch = (const float*)d_in[0];
    const float* mem   = (const float*)d_in[1];
    const int*   topk  = (n_in >= 3) ? (const int*)d_in[2] : nullptr;
    float* out = (float*)d_out;
    (void)in_sizes;

    const int total_warps = NPATCH + MMEM;
    prep_all_kernel<<<(total_warps * 32 + 255) / 256, 256>>>(patch, mem);

    cudaFuncSetAttribute(hmma_gemm_max_kernel,
                         cudaFuncAttributeMaxDynamicSharedMemorySize, SM_TOTAL);
    hmma_gemm_max_kernel<<<PCTAS, 256, SM_TOTAL>>>();

    finalize_kernel<<<1, 256>>>(topk, out, out_size);
}